// round 11
// baseline (speedup 1.0000x reference)
#include <cuda_runtime.h>
#include <cstdint>
#include <cstddef>

// ---------------------------------------------------------------------------
// DataDependentRBFKernel — two kernels, each shaped for its limiter.
//   sigma_kernel: 16 rows / 256-thread block (2 rows per warp), grid 512.
//                 Only w1+w2 in smem (35 KB -> 6 blocks/SM possible);
//                 e streamed via __ldg float4. Writes (sc,c0,c1,cc).
//   rbf_kernel:   proven 8 rows x 1024 z shape, grid (2,1024), but
//                 __launch_bounds__(256,8) -> <=32 regs -> 8 blocks/SM.
// ---------------------------------------------------------------------------

#define EDIM 256
#define H1DIM 32
#define H2DIM 16
#define SROWS 16

__device__ float4 g_coef[8192];   // per-row (sc, c0, c1, cc)

__device__ __forceinline__ float ex2_approx(float x) {
    float y;
    asm("ex2.approx.f32 %0, %1;" : "=f"(y) : "f"(x));
    return y;
}
__device__ __forceinline__ float gelu_exact(float x) {
    return 0.5f * x * (1.0f + erff(x * 0.70710678118654752440f));
}

// -------------------- sigma MLP: 16 rows per 256-thread block --------------
__global__ __launch_bounds__(256)
void sigma_kernel(const float* __restrict__ emb, const float* __restrict__ mu,
                  const float* __restrict__ w1, const float* __restrict__ b1,
                  const float* __restrict__ w2, const float* __restrict__ b2,
                  const float* __restrict__ w3, const float* __restrict__ b3)
{
    __shared__ float w1_s[EDIM * H1DIM];    // 32 KB  [k][j], j contiguous
    __shared__ float w2_s[H1DIM * H2DIM];   // 2 KB
    __shared__ float h1_s[SROWS * H1DIM];   // 2 KB
    __shared__ float h2_s[SROWS * H2DIM];   // 1 KB

    const int tid = threadIdx.x;
    const int rowbase = blockIdx.x * SROWS;

    // stage w1 (2048 float4 / 256 thr) + w2
    {
        const float4* w14 = reinterpret_cast<const float4*>(w1);
        float4* w1s4 = reinterpret_cast<float4*>(w1_s);
        #pragma unroll
        for (int i = 0; i < (EDIM * H1DIM / 4) / 256; ++i)   // 8
            w1s4[tid + i * 256] = w14[tid + i * 256];
        if (tid < (H1DIM * H2DIM / 4))
            reinterpret_cast<float4*>(w2_s)[tid] =
                reinterpret_cast<const float4*>(w2)[tid];
    }
    __syncthreads();

    // ---- layer 1: warp w -> rows 2w, 2w+1; lane = unit j ----
    {
        const int j = tid & 31;
        const int w = tid >> 5;            // 0..7
        const float* e0 = emb + (size_t)(rowbase + 2 * w) * EDIM;
        const float* e1 = e0 + EDIM;

        float acc0, acc1;
        acc0 = acc1 = __ldg(&b1[j]);

        #pragma unroll 8
        for (int k = 0; k < EDIM; k += 4) {
            const float wv0 = w1_s[(k + 0) * H1DIM + j];
            const float wv1 = w1_s[(k + 1) * H1DIM + j];
            const float wv2 = w1_s[(k + 2) * H1DIM + j];
            const float wv3 = w1_s[(k + 3) * H1DIM + j];
            float4 e;
            e = __ldg(reinterpret_cast<const float4*>(e0 + k));
            acc0 = fmaf(e.x, wv0, acc0); acc0 = fmaf(e.y, wv1, acc0);
            acc0 = fmaf(e.z, wv2, acc0); acc0 = fmaf(e.w, wv3, acc0);
            e = __ldg(reinterpret_cast<const float4*>(e1 + k));
            acc1 = fmaf(e.x, wv0, acc1); acc1 = fmaf(e.y, wv1, acc1);
            acc1 = fmaf(e.z, wv2, acc1); acc1 = fmaf(e.w, wv3, acc1);
        }
        h1_s[(2 * w + 0) * H1DIM + j] = gelu_exact(acc0);
        h1_s[(2 * w + 1) * H1DIM + j] = gelu_exact(acc1);
    }
    __syncthreads();

    // ---- layer 2: 16 rows x 16 units = 256 items, 1 per thread ----
    {
        const int r = tid >> 4;
        const int m = tid & 15;
        float acc = __ldg(&b2[m]);
        #pragma unroll
        for (int j = 0; j < H1DIM; ++j)
            acc = fmaf(h1_s[r * H1DIM + j], w2_s[j * H2DIM + m], acc);
        h2_s[r * H2DIM + m] = gelu_exact(acc);
    }
    __syncthreads();

    // ---- layer 3 + sigmoid + affine + fold mu -> g_coef ----
    if (tid < SROWS) {
        float s = __ldg(&b3[0]);
        #pragma unroll
        for (int m = 0; m < H2DIM; ++m)
            s = fmaf(h2_s[tid * H2DIM + m], __ldg(&w3[m]), s);
        const float sig = 1.0f / (1.0f + expf(-s));
        const float sigma = 0.1f + 9.9f * sig;
        const float sc = -1.44269504088896340736f / (2.0f * sigma * sigma);
        const float2 muv = reinterpret_cast<const float2*>(mu)[rowbase + tid];
        const float c0 = -2.0f * sc * muv.x;
        const float c1 = -2.0f * sc * muv.y;
        const float cc = sc * (muv.x * muv.x + muv.y * muv.y);
        g_coef[rowbase + tid] = make_float4(sc, c0, c1, cc);
    }
}

// -------------------- RBF sweep: 8 rows x 1024 z per 256-thread block ------
// Proven shape; min-blocks 8 forces <=32 regs -> up to 64 warps/SM.
__global__ __launch_bounds__(256, 8)
void rbf_kernel(const float* __restrict__ z, float* __restrict__ out, int M)
{
    constexpr int TILE_R = 8;

    const int t = threadIdx.x;
    const int zb = blockIdx.x * 1024 + t * 4;
    const int rowbase = blockIdx.y * TILE_R;

    // 4 z points: z is [M,2] interleaved -> 2 float4 loads
    float z0[4], z1[4], r2[4];
    {
        const float4* z4 = reinterpret_cast<const float4*>(z);
        #pragma unroll
        for (int i = 0; i < 2; ++i) {
            float4 v = __ldg(&z4[(size_t)(blockIdx.x * 512) + (size_t)t * 2 + i]);
            z0[2 * i]     = v.x;  z1[2 * i]     = v.y;
            z0[2 * i + 1] = v.z;  z1[2 * i + 1] = v.w;
        }
        #pragma unroll
        for (int i = 0; i < 4; ++i)
            r2[i] = z0[i] * z0[i] + z1[i] * z1[i];
    }

    float* optr = out + (size_t)rowbase * (size_t)M + (size_t)zb;

    #pragma unroll
    for (int r = 0; r < TILE_R; ++r) {
        const float4 c = __ldg(&g_coef[rowbase + r]);   // uniform -> broadcast
        float o[4];
        #pragma unroll
        for (int i = 0; i < 4; ++i) {
            float a = fmaf(c.x, r2[i], fmaf(c.y, z0[i], fmaf(c.z, z1[i], c.w)));
            o[i] = ex2_approx(a);
        }
        *reinterpret_cast<float4*>(optr) = make_float4(o[0], o[1], o[2], o[3]);
        optr += M;
    }
}

// ---------------------------------------------------------------------------
extern "C" void kernel_launch(void* const* d_in, const int* in_sizes, int n_in,
                              void* d_out, int out_size)
{
    const float* z   = (const float*)d_in[0];   // [M, 2]
    const float* mu  = (const float*)d_in[1];   // [B, N, 2]
    const float* emb = (const float*)d_in[2];   // [B, N, 256]
    const float* w1  = (const float*)d_in[3];   // [256, 32]
    const float* b1  = (const float*)d_in[4];   // [32]
    const float* w2  = (const float*)d_in[5];   // [32, 16]
    const float* b2  = (const float*)d_in[6];   // [16]
    const float* w3  = (const float*)d_in[7];   // [16, 1]
    const float* b3  = (const float*)d_in[8];   // [1]
    float* out = (float*)d_out;

    const int M  = in_sizes[0] / 2;   // 2048
    const int BN = in_sizes[1] / 2;   // 8192

    sigma_kernel<<<BN / SROWS, 256>>>(emb, mu, w1, b1, w2, b2, w3, b3);

    dim3 grid(M / 1024, BN / 8);
    rbf_kernel<<<grid, 256>>>(z, out, M);
}

// round 12
// speedup vs baseline: 1.3253x; 1.3253x over previous
#include <cuda_runtime.h>
#include <cstdint>
#include <cstddef>

// ---------------------------------------------------------------------------
// DataDependentRBFKernel — two kernels.
//   sigma_kernel: grid 128, 64 rows/block (2 serial 32-row tiles), one block
//                 per SM -> uniform load, w1 staged once. e+w1 in smem.
//   rbf_kernel:   proven R6 shape: 8 rows x 1024 z, 4 pts/thread, grid
//                 (2,1024), 40 regs, coef via uniform __ldg.
// ---------------------------------------------------------------------------

#define EDIM 256
#define H1DIM 32
#define H2DIM 16
#define BROWS 64          // rows per sigma block
#define TROWS 32          // rows per tile

__device__ float4 g_coef[8192];   // per-row (sc, c0, c1, cc)

__device__ __forceinline__ float ex2_approx(float x) {
    float y;
    asm("ex2.approx.f32 %0, %1;" : "=f"(y) : "f"(x));
    return y;
}
__device__ __forceinline__ float gelu_exact(float x) {
    return 0.5f * x * (1.0f + erff(x * 0.70710678118654752440f));
}

// smem (floats): e_s[32*256]=32KB | w1_s[256*32]=32KB ([k][j]) |
//                w2_s[32*16]=2KB  | h1_s[64*32]=8KB | h2_s[64*16]=4KB
#define SIG_SMEM_FLOATS (TROWS*EDIM + EDIM*H1DIM + H1DIM*H2DIM + BROWS*H1DIM + BROWS*H2DIM)

__global__ __launch_bounds__(256)
void sigma_kernel(const float* __restrict__ emb, const float* __restrict__ mu,
                  const float* __restrict__ w1, const float* __restrict__ b1,
                  const float* __restrict__ w2, const float* __restrict__ b2,
                  const float* __restrict__ w3, const float* __restrict__ b3)
{
    extern __shared__ float smem[];
    float* e_s  = smem;                        // 8192
    float* w1_s = e_s + TROWS * EDIM;          // 8192
    float* w2_s = w1_s + EDIM * H1DIM;         // 512
    float* h1_s = w2_s + H1DIM * H2DIM;        // 2048 (64 rows)
    float* h2_s = h1_s + BROWS * H1DIM;        // 1024 (64 rows)

    const int tid = threadIdx.x;
    const int rowbase = blockIdx.x * BROWS;

    // ---- stage w1 + w2 once ----
    {
        const float4* w14 = reinterpret_cast<const float4*>(w1);
        float4* w1s4 = reinterpret_cast<float4*>(w1_s);
        #pragma unroll
        for (int i = 0; i < (EDIM * H1DIM / 4) / 256; ++i)   // 8
            w1s4[tid + i * 256] = w14[tid + i * 256];
        if (tid < (H1DIM * H2DIM / 4))
            reinterpret_cast<float4*>(w2_s)[tid] =
                reinterpret_cast<const float4*>(w2)[tid];
    }

    // ---- two serial 32-row tiles ----
    #pragma unroll
    for (int tile = 0; tile < BROWS / TROWS; ++tile) {
        const int trowbase = rowbase + tile * TROWS;

        // stage e tile (2048 float4 / 256 thr = 8 each)
        {
            const float4* e4 = reinterpret_cast<const float4*>(
                emb + (size_t)trowbase * EDIM);
            float4* es4 = reinterpret_cast<float4*>(e_s);
            #pragma unroll
            for (int i = 0; i < (TROWS * EDIM / 4) / 256; ++i)   // 8
                es4[tid + i * 256] = e4[tid + i * 256];
        }
        __syncthreads();

        // layer 1: warp w -> rows 4w..4w+3, lane = unit j
        {
            const int j = tid & 31;
            const int w = tid >> 5;            // 0..7
            const float* e0 = e_s + (w * 4) * EDIM;
            float* h1o = h1_s + (tile * TROWS + w * 4) * H1DIM;

            float acc0, acc1, acc2, acc3;
            acc0 = acc1 = acc2 = acc3 = __ldg(&b1[j]);

            #pragma unroll 8
            for (int k = 0; k < EDIM; k += 4) {
                const float wv0 = w1_s[(k + 0) * H1DIM + j];
                const float wv1 = w1_s[(k + 1) * H1DIM + j];
                const float wv2 = w1_s[(k + 2) * H1DIM + j];
                const float wv3 = w1_s[(k + 3) * H1DIM + j];
                float4 e;
                e = *reinterpret_cast<const float4*>(e0 + 0 * EDIM + k);
                acc0 = fmaf(e.x, wv0, acc0); acc0 = fmaf(e.y, wv1, acc0);
                acc0 = fmaf(e.z, wv2, acc0); acc0 = fmaf(e.w, wv3, acc0);
                e = *reinterpret_cast<const float4*>(e0 + 1 * EDIM + k);
                acc1 = fmaf(e.x, wv0, acc1); acc1 = fmaf(e.y, wv1, acc1);
                acc1 = fmaf(e.z, wv2, acc1); acc1 = fmaf(e.w, wv3, acc1);
                e = *reinterpret_cast<const float4*>(e0 + 2 * EDIM + k);
                acc2 = fmaf(e.x, wv0, acc2); acc2 = fmaf(e.y, wv1, acc2);
                acc2 = fmaf(e.z, wv2, acc2); acc2 = fmaf(e.w, wv3, acc2);
                e = *reinterpret_cast<const float4*>(e0 + 3 * EDIM + k);
                acc3 = fmaf(e.x, wv0, acc3); acc3 = fmaf(e.y, wv1, acc3);
                acc3 = fmaf(e.z, wv2, acc3); acc3 = fmaf(e.w, wv3, acc3);
            }
            h1o[0 * H1DIM + j] = gelu_exact(acc0);
            h1o[1 * H1DIM + j] = gelu_exact(acc1);
            h1o[2 * H1DIM + j] = gelu_exact(acc2);
            h1o[3 * H1DIM + j] = gelu_exact(acc3);
        }
        __syncthreads();   // protects e_s reuse next tile + h1 visibility
    }

    // ---- layer 2: 64 rows x 16 units = 1024 items, 4 per thread ----
    {
        #pragma unroll
        for (int it = 0; it < 4; ++it) {
            const int item = tid + it * 256;
            const int r = item >> 4;
            const int m = item & 15;
            float acc = __ldg(&b2[m]);
            #pragma unroll
            for (int j = 0; j < H1DIM; ++j)
                acc = fmaf(h1_s[r * H1DIM + j], w2_s[j * H2DIM + m], acc);
            h2_s[r * H2DIM + m] = gelu_exact(acc);
        }
    }
    __syncthreads();

    // ---- layer 3 + sigmoid + affine + fold mu -> g_coef ----
    if (tid < BROWS) {
        float s = __ldg(&b3[0]);
        #pragma unroll
        for (int m = 0; m < H2DIM; ++m)
            s = fmaf(h2_s[tid * H2DIM + m], __ldg(&w3[m]), s);
        const float sig = 1.0f / (1.0f + expf(-s));
        const float sigma = 0.1f + 9.9f * sig;
        const float sc = -1.44269504088896340736f / (2.0f * sigma * sigma);
        const float2 muv = reinterpret_cast<const float2*>(mu)[rowbase + tid];
        const float c0 = -2.0f * sc * muv.x;
        const float c1 = -2.0f * sc * muv.y;
        const float cc = sc * (muv.x * muv.x + muv.y * muv.y);
        g_coef[rowbase + tid] = make_float4(sc, c0, c1, cc);
    }
}

// -------------------- RBF sweep: 8 rows x 1024 z per 256-thread block ------
// Proven R6 kernel (12.48 us): 40 regs, occ ~59%, no smem/barrier.
__global__ __launch_bounds__(256)
void rbf_kernel(const float* __restrict__ z, float* __restrict__ out, int M)
{
    constexpr int TILE_R = 8;

    const int t = threadIdx.x;
    const int zb = blockIdx.x * 1024 + t * 4;
    const int rowbase = blockIdx.y * TILE_R;

    float z0[4], z1[4], r2[4];
    {
        const float4* z4 = reinterpret_cast<const float4*>(z);
        #pragma unroll
        for (int i = 0; i < 2; ++i) {
            float4 v = __ldg(&z4[(size_t)(blockIdx.x * 512) + (size_t)t * 2 + i]);
            z0[2 * i]     = v.x;  z1[2 * i]     = v.y;
            z0[2 * i + 1] = v.z;  z1[2 * i + 1] = v.w;
        }
        #pragma unroll
        for (int i = 0; i < 4; ++i)
            r2[i] = z0[i] * z0[i] + z1[i] * z1[i];
    }

    float* optr = out + (size_t)rowbase * (size_t)M + (size_t)zb;

    #pragma unroll
    for (int r = 0; r < TILE_R; ++r) {
        const float4 c = __ldg(&g_coef[rowbase + r]);   // uniform -> broadcast
        float o[4];
        #pragma unroll
        for (int i = 0; i < 4; ++i) {
            float a = fmaf(c.x, r2[i], fmaf(c.y, z0[i], fmaf(c.z, z1[i], c.w)));
            o[i] = ex2_approx(a);
        }
        *reinterpret_cast<float4*>(optr) = make_float4(o[0], o[1], o[2], o[3]);
        optr += M;
    }
}

// ---------------------------------------------------------------------------
extern "C" void kernel_launch(void* const* d_in, const int* in_sizes, int n_in,
                              void* d_out, int out_size)
{
    const float* z   = (const float*)d_in[0];   // [M, 2]
    const float* mu  = (const float*)d_in[1];   // [B, N, 2]
    const float* emb = (const float*)d_in[2];   // [B, N, 256]
    const float* w1  = (const float*)d_in[3];   // [256, 32]
    const float* b1  = (const float*)d_in[4];   // [32]
    const float* w2  = (const float*)d_in[5];   // [32, 16]
    const float* b2  = (const float*)d_in[6];   // [16]
    const float* w3  = (const float*)d_in[7];   // [16, 1]
    const float* b3  = (const float*)d_in[8];   // [1]
    float* out = (float*)d_out;

    const int M  = in_sizes[0] / 2;   // 2048
    const int BN = in_sizes[1] / 2;   // 8192

    const int smem_bytes = SIG_SMEM_FLOATS * sizeof(float);
    static bool attr_set = false;
    if (!attr_set) {
        cudaFuncSetAttribute(sigma_kernel,
                             cudaFuncAttributeMaxDynamicSharedMemorySize,
                             smem_bytes);
        attr_set = true;
    }

    sigma_kernel<<<BN / BROWS, 256, smem_bytes>>>(emb, mu, w1, b1, w2, b2, w3, b3);

    dim3 grid(M / 1024, BN / 8);
    rbf_kernel<<<grid, 256>>>(z, out, M);
}